// round 9
// baseline (speedup 1.0000x reference)
#include <cuda_runtime.h>
#include <math.h>
#include <stdint.h>

// ---------------- problem constants ----------------
#define Dm   768
#define Hh   12
#define HDm  64
#define Mm   3072
#define Lm   12
#define Em   8
#define Km   2
#define Bm   32
#define Sm   196
#define GSm  392
#define NGm  16
#define CAPm 98
#define NTOK (Bm*Sm)     // 6272
#define EROWS (NGm*CAPm) // 1568
#define TROWS (Em*EROWS) // 12544
#define K2D  (Dm/2)      // 384 k-pairs
#define K2M  (Mm/2)      // 1536 k-pairs

// ---------------- scratch ----------------
__device__ float g_x [(size_t)NTOK*Dm];
__device__ float g_h [(size_t)NTOK*Dm];
__device__ float g_q [(size_t)NTOK*Dm];
__device__ float g_k [(size_t)NTOK*Dm];
__device__ float g_v [(size_t)NTOK*Dm];
__device__ float g_y [(size_t)TROWS*Dm];
// bf16-split interleaved (hi,lo) uint2 per k-pair
__device__ uint2 g_h_sp [(size_t)NTOK*K2D];
__device__ uint2 g_ao_sp[(size_t)NTOK*K2D];
__device__ uint2 g_ml_sp[(size_t)NTOK*K2M];
__device__ uint2 g_bf_sp[(size_t)(TROWS+128)*K2D];
__device__ uint2 g_hx_sp[(size_t)(TROWS+128)*K2M];
__device__ uint2 g_wsp  [(size_t)Em*K2D*Mm];
__device__ int   g_slot_src[TROWS];
__device__ int   g_comb_idx[NTOK*Km];
__device__ float g_comb_gate[NTOK*Km];

// ---------------- helpers ----------------
__device__ __forceinline__ float gelu_f(float x) {
    const float c = 0.7978845608028654f;
    float t = tanhf(c * (x + 0.044715f * x * x * x));
    return 0.5f * x * (1.0f + t);
}

__device__ __forceinline__ uint32_t smem_u32(const void* p) {
    uint32_t a;
    asm("{ .reg .u64 t; cvta.to.shared.u64 t, %1; cvt.u32.u64 %0, t; }" : "=r"(a) : "l"(p));
    return a;
}

__device__ __forceinline__ void cp16(uint32_t dst, const void* src, uint32_t sz) {
    asm volatile("cp.async.ca.shared.global [%0], [%1], 16, %2;"
                 :: "r"(dst), "l"(src), "r"(sz));
}
#define CP_COMMIT() asm volatile("cp.async.commit_group;" ::: "memory")
#define CP_WAIT(n)  asm volatile("cp.async.wait_group %0;" :: "n"(n) : "memory")

__device__ __forceinline__ void mma16(float* c, const uint32_t* a, const uint32_t* b) {
    asm volatile(
        "mma.sync.aligned.m16n8k16.row.col.f32.bf16.bf16.f32 "
        "{%0,%1,%2,%3},{%4,%5,%6,%7},{%8,%9},{%0,%1,%2,%3};"
        : "+f"(c[0]), "+f"(c[1]), "+f"(c[2]), "+f"(c[3])
        : "r"(a[0]), "r"(a[1]), "r"(a[2]), "r"(a[3]), "r"(b[0]), "r"(b[1]));
}

// pack two floats (x0=even k -> lo16, x1=odd k -> hi16)
__device__ __forceinline__ uint32_t packbf(float x1, float x0) {
    uint32_t d;
    asm("cvt.rn.bf16x2.f32 %0, %1, %2;" : "=r"(d) : "f"(x1), "f"(x0));
    return d;
}
__device__ __forceinline__ uint2 split_bf(float x0, float x1) {
    uint2 r;
    r.x = packbf(x1, x0);
    float h0 = __uint_as_float(r.x << 16);
    float h1 = __uint_as_float(r.x & 0xFFFF0000u);
    r.y = packbf(x1 - h1, x0 - h0);
    return r;
}

// ---------------- weight split prepass: W[K][P] -> uint2[K/2][P] ----------
__global__ void wsplit_kernel(const float* __restrict__ w, uint2* __restrict__ out,
                              int P, long np) {
    long j = ((long)blockIdx.x * blockDim.x + threadIdx.x) * 4;
    if (j >= np) return;
    long k2 = j / P;
    int n = (int)(j - k2 * P);
    const float* r0 = w + (2 * k2) * (long)P + n;
    float4 a = *reinterpret_cast<const float4*>(r0);
    float4 b = *reinterpret_cast<const float4*>(r0 + P);
    uint2 s0 = split_bf(a.x, b.x), s1 = split_bf(a.y, b.y);
    uint2 s2 = split_bf(a.z, b.z), s3 = split_bf(a.w, b.w);
    *reinterpret_cast<uint4*>(out + j)     = make_uint4(s0.x, s0.y, s1.x, s1.y);
    *reinterpret_cast<uint4*>(out + j + 2) = make_uint4(s2.x, s2.y, s3.x, s3.y);
}

// ---------------- 3xBF16 GEMM (interleaved uint2 operands) ----------------
// chunk = 16 k-pairs (K=32). A smem [2][128][20 uint2]; B smem [2][16][132 uint2]
#define KCH  16
#define AST  20
#define BST  132
#define A_U2 (128*AST)    // 2560
#define B_U2 (KCH*BST)    // 2112
#define GEMM_SMEM ((2*A_U2 + 2*B_U2)*8)   // 74752 bytes

__global__ void __launch_bounds__(256, 2)
mma_gemm(const uint2* __restrict__ A, const uint2* __restrict__ W,
         const float* __restrict__ bias,
         float* __restrict__ Cf, uint2* __restrict__ Csp,
         int Nrows, int K2, int Pc,
         long strA, long strW, long strBias, long strC,
         float alpha, int act, int accum) {
    int z = blockIdx.z;
    A += (long)z * strA; W += (long)z * strW;
    const float* Bp = bias + (long)z * strBias;

    extern __shared__ uint2 smu[];
    uint2* Asm = smu;                // [2][A_U2]
    uint2* Bsm = smu + 2 * A_U2;     // [2][B_U2]

    int tid = threadIdx.x;
    int row0 = blockIdx.y * 128, col0 = blockIdx.x * 128;

    // staging: A 2 threads/row, each 8 uint2 (4 cp16); B 16 threads/row, each 8 uint2
    int ar = tid >> 1, ako = (tid & 1) * 8;
    int bkr = tid >> 4, bno = (tid & 15) * 8;
    const uint2* gA = A + (long)(row0 + ar) * K2 + ako;
    const uint2* gB = W + (long)bkr * Pc + col0 + bno;
    uint32_t asz = ((row0 + ar) < Nrows) ? 16u : 0u;
    uint32_t dA = smem_u32(Asm) + (uint32_t)(ar * AST + ako) * 8u;
    uint32_t dB = smem_u32(Bsm) + (uint32_t)(bkr * BST + bno) * 8u;
    long bstep = (long)KCH * Pc;

    int nk = K2 / KCH;

    #pragma unroll
    for (int j = 0; j < 4; j++) cp16(dA + j * 16, gA + j * 2, asz);
    #pragma unroll
    for (int j = 0; j < 4; j++) cp16(dB + j * 16, gB + j * 2, 16);
    CP_COMMIT();

    int warp = tid >> 5, lane = tid & 31;
    int wm = (warp & 3) * 32, wn = (warp >> 2) * 64;
    int gid = lane >> 2, tig = lane & 3;

    float acc[2][8][4];
    #pragma unroll
    for (int mt = 0; mt < 2; mt++)
        #pragma unroll
        for (int nt = 0; nt < 8; nt++)
            #pragma unroll
            for (int r = 0; r < 4; r++) acc[mt][nt][r] = 0.0f;

    for (int i = 0; i < nk; i++) {
        int b = i & 1;
        if (i + 1 < nk) {
            int nb = b ^ 1;
            const uint2* pa = gA + (long)(i + 1) * KCH;
            const uint2* pb = gB + (long)(i + 1) * bstep;
            uint32_t da = dA + (uint32_t)(nb * A_U2) * 8u;
            uint32_t db = dB + (uint32_t)(nb * B_U2) * 8u;
            #pragma unroll
            for (int j = 0; j < 4; j++) cp16(da + j * 16, pa + j * 2, asz);
            #pragma unroll
            for (int j = 0; j < 4; j++) cp16(db + j * 16, pb + j * 2, 16);
            CP_COMMIT();
            CP_WAIT(1);
        } else {
            CP_WAIT(0);
        }
        __syncthreads();

        const uint2* As = Asm + b * A_U2;
        const uint2* Bs = Bsm + b * B_U2;
        #pragma unroll
        for (int ks = 0; ks < 2; ks++) {
            int kq = ks * 8;
            uint32_t afh[2][4], afl[2][4];
            #pragma unroll
            for (int mt = 0; mt < 2; mt++) {
                const uint2* ap = As + (wm + mt * 16 + gid) * AST + kq + tig;
                uint2 v0 = ap[0];
                uint2 v1 = ap[8 * AST];
                uint2 v2 = ap[4];
                uint2 v3 = ap[8 * AST + 4];
                afh[mt][0] = v0.x; afl[mt][0] = v0.y;
                afh[mt][1] = v1.x; afl[mt][1] = v1.y;
                afh[mt][2] = v2.x; afl[mt][2] = v2.y;
                afh[mt][3] = v3.x; afl[mt][3] = v3.y;
            }
            #pragma unroll
            for (int nt = 0; nt < 8; nt++) {
                const uint2* bp = Bs + (kq + tig) * BST + wn + nt * 8 + gid;
                uint2 w0 = bp[0];
                uint2 w1 = bp[4 * BST];
                uint32_t bh[2] = { w0.x, w1.x };
                uint32_t bl[2] = { w0.y, w1.y };
                #pragma unroll
                for (int mt = 0; mt < 2; mt++) {
                    mma16(acc[mt][nt], afh[mt], bl);
                    mma16(acc[mt][nt], afl[mt], bh);
                    mma16(acc[mt][nt], afh[mt], bh);
                }
            }
        }
        __syncthreads();
    }

    // epilogue
    int P2 = Pc >> 1;
    #pragma unroll
    for (int mt = 0; mt < 2; mt++) {
        int r0 = row0 + wm + mt * 16 + gid;
        #pragma unroll
        for (int half = 0; half < 2; half++) {
            int gr = r0 + half * 8;
            if (gr >= Nrows) continue;
            #pragma unroll
            for (int nt = 0; nt < 8; nt++) {
                int gc = col0 + wn + nt * 8 + 2 * tig;
                float2 bv = *reinterpret_cast<const float2*>(Bp + gc);
                float v0 = (acc[mt][nt][half * 2 + 0] + bv.x) * alpha;
                float v1 = (acc[mt][nt][half * 2 + 1] + bv.y) * alpha;
                if (act) { v0 = gelu_f(v0); v1 = gelu_f(v1); }
                if (Csp) {
                    Csp[(long)z * strC + (long)gr * P2 + (gc >> 1)] = split_bf(v0, v1);
                } else {
                    float* Cp = Cf + (long)z * strC + (long)gr * Pc + gc;
                    if (accum) {
                        float2 o = *reinterpret_cast<float2*>(Cp);
                        v0 += o.x; v1 += o.y;
                    }
                    *reinterpret_cast<float2*>(Cp) = make_float2(v0, v1);
                }
            }
        }
    }
}

// ---------------- elementwise ----------------
__global__ void addpos_kernel(const float* __restrict__ x, const float* __restrict__ pe,
                              float* __restrict__ out) {
    int i = blockIdx.x * blockDim.x + threadIdx.x;
    if (i < NTOK * Dm) out[i] = x[i] + pe[i % (Sm * Dm)];
}

__device__ __forceinline__ float block_reduce_sum(float v) {
    __shared__ float sh[33];
    int lane = threadIdx.x & 31, w = threadIdx.x >> 5;
    #pragma unroll
    for (int o = 16; o; o >>= 1) v += __shfl_xor_sync(0xffffffffu, v, o);
    if (lane == 0) sh[w] = v;
    __syncthreads();
    int nw = blockDim.x >> 5;
    float r = (threadIdx.x < nw) ? sh[threadIdx.x] : 0.0f;
    if (w == 0) {
        #pragma unroll
        for (int o = 16; o; o >>= 1) r += __shfl_xor_sync(0xffffffffu, r, o);
        if (lane == 0) sh[32] = r;
    }
    __syncthreads();
    float out = sh[32];
    __syncthreads();
    return out;
}

__global__ void ln_kernel(const float* __restrict__ in, float* __restrict__ outf,
                          uint2* __restrict__ outsp,
                          const float* __restrict__ s, const float* __restrict__ b) {
    int t = blockIdx.x;
    const float* xr = in + (size_t)t * Dm;
    float sum = 0.0f;
    for (int i = threadIdx.x; i < Dm; i += blockDim.x) sum += xr[i];
    float mu = block_reduce_sum(sum) * (1.0f / Dm);
    float vs = 0.0f;
    for (int i = threadIdx.x; i < Dm; i += blockDim.x) { float d = xr[i] - mu; vs += d * d; }
    float var = block_reduce_sum(vs) * (1.0f / Dm);
    float inv = rsqrtf(var + 1e-6f);
    for (int i = threadIdx.x * 2; i < Dm; i += blockDim.x * 2) {
        float v0 = (xr[i] - mu) * inv * s[i] + b[i];
        float v1 = (xr[i + 1] - mu) * inv * s[i + 1] + b[i + 1];
        if (outf) { outf[(size_t)t * Dm + i] = v0; outf[(size_t)t * Dm + i + 1] = v1; }
        if (outsp) outsp[(size_t)t * K2D + (i >> 1)] = split_bf(v0, v1);
    }
}

// ---------------- attention ----------------
#define KPAD (HDm + 1)
__global__ void attn_kernel(const float* __restrict__ q, const float* __restrict__ k,
                            const float* __restrict__ v, uint2* __restrict__ osp) {
    extern __shared__ float sm[];
    float* Ks = sm;
    float* Vs = sm + Sm * KPAD;
    __shared__ float att[8][Sm];
    __shared__ float qrow[8][HDm];

    int bh = blockIdx.x;
    int b = bh / Hh, h = bh % Hh;
    int tid = threadIdx.x, warp = tid >> 5, lane = tid & 31;
    const long base = (long)(b * Sm) * Dm + h * HDm;
    const long base2 = (long)(b * Sm) * K2D + h * (HDm / 2);

    for (int idx = tid; idx < Sm * HDm; idx += blockDim.x) {
        int j = idx >> 6, c = idx & 63;
        Ks[j * KPAD + c] = k[base + (long)j * Dm + c];
        Vs[j * KPAD + c] = v[base + (long)j * Dm + c];
    }
    __syncthreads();

    for (int i = warp; i < Sm; i += 8) {
        for (int c = lane; c < HDm; c += 32) qrow[warp][c] = q[base + (long)i * Dm + c];
        __syncwarp();
        float lmax = -1e30f;
        for (int j = lane; j < Sm; j += 32) {
            float d = 0.0f;
            #pragma unroll
            for (int c = 0; c < HDm; c++) d += qrow[warp][c] * Ks[j * KPAD + c];
            att[warp][j] = d;
            lmax = fmaxf(lmax, d);
        }
        #pragma unroll
        for (int off = 16; off; off >>= 1)
            lmax = fmaxf(lmax, __shfl_xor_sync(0xffffffffu, lmax, off));
        float lsum = 0.0f;
        for (int j = lane; j < Sm; j += 32) {
            float e = expf(att[warp][j] - lmax);
            att[warp][j] = e;
            lsum += e;
        }
        #pragma unroll
        for (int off = 16; off; off >>= 1)
            lsum += __shfl_xor_sync(0xffffffffu, lsum, off);
        float inv = 1.0f / lsum;
        __syncwarp();
        {
            int c = lane * 2;
            float a0 = 0.0f, a1 = 0.0f;
            for (int j = 0; j < Sm; j++) {
                float w = att[warp][j];
                a0 += w * Vs[j * KPAD + c];
                a1 += w * Vs[j * KPAD + c + 1];
            }
            osp[base2 + (long)i * K2D + (c >> 1)] = split_bf(a0 * inv, a1 * inv);
        }
        __syncwarp();
    }
}

// ---------------- MoE routing ----------------
__global__ void route_kernel(const float* __restrict__ h, const float* __restrict__ wr) {
    int n = blockIdx.x;
    __shared__ float wrs[Em * Dm];
    __shared__ float tv[GSm][Km];
    __shared__ int   ti[GSm][Km];
    int tid = threadIdx.x, warp = tid >> 5, lane = tid & 31;

    for (int idx = tid; idx < Em * Dm; idx += blockDim.x) {
        int e = idx / Dm, c = idx % Dm;
        wrs[e * Dm + c] = wr[c * Em + e];
    }
    for (int s = tid; s < Em * CAPm; s += blockDim.x) {
        int e = s / CAPm, c = s % CAPm;
        g_slot_src[(e * NGm + n) * CAPm + c] = -1;
    }
    __syncthreads();

    for (int t = warp; t < GSm; t += 8) {
        const float* xr = h + (long)(n * GSm + t) * Dm;
        float a[Em];
        #pragma unroll
        for (int e = 0; e < Em; e++) a[e] = 0.0f;
        for (int c = lane; c < Dm; c += 32) {
            float xv = xr[c];
            #pragma unroll
            for (int e = 0; e < Em; e++) a[e] += xv * wrs[e * Dm + c];
        }
        #pragma unroll
        for (int e = 0; e < Em; e++)
            #pragma unroll
            for (int o = 16; o; o >>= 1) a[e] += __shfl_xor_sync(0xffffffffu, a[e], o);
        if (lane == 0) {
            float mx = a[0];
            #pragma unroll
            for (int e = 1; e < Em; e++) mx = fmaxf(mx, a[e]);
            float p[Em], sum = 0.0f;
            #pragma unroll
            for (int e = 0; e < Em; e++) { p[e] = expf(a[e] - mx); sum += p[e]; }
            float inv = 1.0f / sum;
            #pragma unroll
            for (int e = 0; e < Em; e++) p[e] *= inv;
            int i0 = 0;
            #pragma unroll
            for (int e = 1; e < Em; e++) if (p[e] > p[i0]) i0 = e;
            int i1 = (i0 == 0) ? 1 : 0;
            #pragma unroll
            for (int e = 0; e < Em; e++) if (e != i0 && p[e] > p[i1]) i1 = e;
            ti[t][0] = i0; tv[t][0] = p[i0];
            ti[t][1] = i1; tv[t][1] = p[i1];
        }
    }
    __syncthreads();

    if (tid == 0) {
        int cnt[Em];
        #pragma unroll
        for (int e = 0; e < Em; e++) cnt[e] = 0;
        for (int kk = 0; kk < Km; kk++) {
            for (int t = 0; t < GSm; t++) {
                int e = ti[t][kk];
                int pos = cnt[e]++;
                int gt = n * GSm + t;
                if (pos < CAPm) {
                    int row = (e * NGm + n) * CAPm + pos;
                    g_slot_src[row] = gt;
                    g_comb_idx[gt * Km + kk] = row;
                    g_comb_gate[gt * Km + kk] = tv[t][kk];
                } else {
                    g_comb_idx[gt * Km + kk] = -1;
                    g_comb_gate[gt * Km + kk] = 0.0f;
                }
            }
        }
    }
}

__global__ void gather_kernel(const float* __restrict__ h) {
    int i = blockIdx.x * blockDim.x + threadIdx.x;
    if (i >= TROWS * K2D) return;
    int row = i / K2D, kp = i - row * K2D;
    int src = g_slot_src[row];
    float v0 = 0.0f, v1 = 0.0f;
    if (src >= 0) {
        float2 p = *reinterpret_cast<const float2*>(h + (long)src * Dm + 2 * kp);
        v0 = p.x; v1 = p.y;
    }
    g_bf_sp[i] = split_bf(v0, v1);
}

__global__ void combine_kernel(float* __restrict__ x) {
    int i = blockIdx.x * blockDim.x + threadIdx.x;
    if (i >= NTOK * Dm) return;
    int t = i / Dm, c = i - t * Dm;
    float acc = 0.0f;
    #pragma unroll
    for (int kk = 0; kk < Km; kk++) {
        int r = g_comb_idx[t * Km + kk];
        if (r >= 0) acc += g_comb_gate[t * Km + kk] * g_y[(long)r * Dm + c];
    }
    x[i] += acc;
}

// ---------------- host ----------------
static inline void wsplit(const float* w, uint2* dst, int P, long np) {
    wsplit_kernel<<<(unsigned)((np / 4 + 255) / 256), 256>>>(w, dst, P, np);
}

extern "C" void kernel_launch(void* const* d_in, const int* in_sizes, int n_in,
                              void* d_out, int out_size) {
    (void)in_sizes; (void)n_in; (void)out_size;
    const float* in_x     = (const float*)d_in[0];
    const float* posemb   = (const float*)d_in[1];
    const float* ln1_s    = (const float*)d_in[2];
    const float* ln1_b    = (const float*)d_in[3];
    const float* wq       = (const float*)d_in[4];
    const float* bq       = (const float*)d_in[5];
    const float* wk       = (const float*)d_in[6];
    const float* bk       = (const float*)d_in[7];
    const float* wv       = (const float*)d_in[8];
    const float* bv       = (const float*)d_in[9];
    const float* wo       = (const float*)d_in[10];
    const float* bo       = (const float*)d_in[11];
    const float* ln2_s    = (const float*)d_in[12];
    const float* ln2_b    = (const float*)d_in[13];
    const float* dw1      = (const float*)d_in[14];
    const float* db1      = (const float*)d_in[15];
    const float* dw2      = (const float*)d_in[16];
    const float* db2      = (const float*)d_in[17];
    const float* router_w = (const float*)d_in[18];
    const float* mw1      = (const float*)d_in[19];
    const float* mb1      = (const float*)d_in[20];
    const float* mw2      = (const float*)d_in[21];
    const float* mb2      = (const float*)d_in[22];
    const float* out_s    = (const float*)d_in[23];
    const float* out_b    = (const float*)d_in[24];
    float* out = (float*)d_out;

    float *x, *h, *q, *k, *v, *y;
    uint2 *h_sp, *ao_sp, *ml_sp, *bf_sp, *hx_sp, *wsp;
    cudaGetSymbolAddress((void**)&x,     g_x);
    cudaGetSymbolAddress((void**)&h,     g_h);
    cudaGetSymbolAddress((void**)&q,     g_q);
    cudaGetSymbolAddress((void**)&k,     g_k);
    cudaGetSymbolAddress((void**)&v,     g_v);
    cudaGetSymbolAddress((void**)&y,     g_y);
    cudaGetSymbolAddress((void**)&h_sp,  g_h_sp);
    cudaGetSymbolAddress((void**)&ao_sp, g_ao_sp);
    cudaGetSymbolAddress((void**)&ml_sp, g_ml_sp);
    cudaGetSymbolAddress((void**)&bf_sp, g_bf_sp);
    cudaGetSymbolAddress((void**)&hx_sp, g_hx_sp);
    cudaGetSymbolAddress((void**)&wsp,   g_wsp);

    const int ATTN_SMEM = 2 * Sm * KPAD * (int)sizeof(float);
    cudaFuncSetAttribute(attn_kernel, cudaFuncAttributeMaxDynamicSharedMemorySize, ATTN_SMEM);
    cudaFuncSetAttribute(mma_gemm, cudaFuncAttributeMaxDynamicSharedMemorySize, GEMM_SMEM);

    const float qscale = 0.125f;
    const long WDD = (long)Dm * Dm;
    const long WDM = (long)Dm * Mm;

    addpos_kernel<<<(NTOK * Dm + 255) / 256, 256>>>(in_x, posemb, x);

    int di = 0, mi = 0;
    for (int l = 0; l < Lm; l++) {
        // ---- attention block ----
        ln_kernel<<<NTOK, 256>>>(x, nullptr, h_sp,
                                 ln1_s + (size_t)l * Dm, ln1_b + (size_t)l * Dm);
        dim3 gdd(Dm / 128, NTOK / 128, 1);
        wsplit(wq + (size_t)l * WDD, wsp, Dm, WDD / 2);
        mma_gemm<<<gdd, 256, GEMM_SMEM>>>(h_sp, wsp, bq + (size_t)l * Dm, q, nullptr,
                                          NTOK, K2D, Dm, 0, 0, 0, 0, qscale, 0, 0);
        wsplit(wk + (size_t)l * WDD, wsp, Dm, WDD / 2);
        mma_gemm<<<gdd, 256, GEMM_SMEM>>>(h_sp, wsp, bk + (size_t)l * Dm, k, nullptr,
                                          NTOK, K2D, Dm, 0, 0, 0, 0, 1.0f, 0, 0);
        wsplit(wv + (size_t)l * WDD, wsp, Dm, WDD / 2);
        mma_gemm<<<gdd, 256, GEMM_SMEM>>>(h_sp, wsp, bv + (size_t)l * Dm, v, nullptr,
                                          NTOK, K2D, Dm, 0, 0, 0, 0, 1.0f, 0, 0);
        attn_kernel<<<Bm * Hh, 256, ATTN_SMEM>>>(q, k, v, ao_sp);
        wsplit(wo + (size_t)l * WDD, wsp, Dm, WDD / 2);
        mma_gemm<<<gdd, 256, GEMM_SMEM>>>(ao_sp, wsp, bo + (size_t)l * Dm, x, nullptr,
                                          NTOK, K2D, Dm, 0, 0, 0, 0, 1.0f, 0, 1);

        // ---- mlp / moe block ----
        ln_kernel<<<NTOK, 256>>>(x, h, h_sp,
                                 ln2_s + (size_t)l * Dm, ln2_b + (size_t)l * Dm);
        if (l & 1) {
            route_kernel<<<NGm, 256>>>(h, router_w + (size_t)mi * Dm * Em);
            gather_kernel<<<(TROWS * K2D + 255) / 256, 256>>>(h);
            wsplit(mw1 + (size_t)mi * Em * WDM, wsp, Mm, (long)Em * WDM / 2);
            dim3 g1(Mm / 128, (EROWS + 127) / 128, Em);
            mma_gemm<<<g1, 256, GEMM_SMEM>>>(bf_sp, wsp, mb1 + (size_t)mi * Em * Mm,
                                             nullptr, hx_sp,
                                             EROWS, K2D, Mm,
                                             (long)EROWS * K2D, (long)K2D * Mm, Mm,
                                             (long)EROWS * K2M, 1.0f, 1, 0);
            wsplit(mw2 + (size_t)mi * Em * WDM, wsp, Dm, (long)Em * WDM / 2);
            dim3 g2(Dm / 128, (EROWS + 127) / 128, Em);
            mma_gemm<<<g2, 256, GEMM_SMEM>>>(hx_sp, wsp, mb2 + (size_t)mi * Em * Dm,
                                             y, nullptr,
                                             EROWS, K2M, Dm,
                                             (long)EROWS * K2M, (long)K2M * Dm, Dm,
                                             (long)EROWS * Dm, 1.0f, 0, 0);
            combine_kernel<<<(NTOK * Dm + 255) / 256, 256>>>(x);
            mi++;
        } else {
            wsplit(dw1 + (size_t)di * WDM, wsp, Mm, WDM / 2);
            dim3 g1(Mm / 128, NTOK / 128, 1);
            mma_gemm<<<g1, 256, GEMM_SMEM>>>(h_sp, wsp, db1 + (size_t)di * Mm,
                                             nullptr, ml_sp,
                                             NTOK, K2D, Mm, 0, 0, 0, 0, 1.0f, 1, 0);
            wsplit(dw2 + (size_t)di * WDM, wsp, Dm, WDM / 2);
            dim3 g2(Dm / 128, NTOK / 128, 1);
            mma_gemm<<<g2, 256, GEMM_SMEM>>>(ml_sp, wsp, db2 + (size_t)di * Dm,
                                             x, nullptr,
                                             NTOK, K2M, Dm, 0, 0, 0, 0, 1.0f, 0, 1);
            di++;
        }
    }

    ln_kernel<<<NTOK, 256>>>(x, out, nullptr, out_s, out_b);
}

// round 11
// speedup vs baseline: 1.0972x; 1.0972x over previous
#include <cuda_runtime.h>
#include <math.h>
#include <stdint.h>

// ---------------- problem constants ----------------
#define Dm   768
#define Hh   12
#define HDm  64
#define Mm   3072
#define Lm   12
#define Em   8
#define Km   2
#define Bm   32
#define Sm   196
#define GSm  392
#define NGm  16
#define CAPm 98
#define NTOK (Bm*Sm)     // 6272
#define EROWS (NGm*CAPm) // 1568
#define TROWS (Em*EROWS) // 12544
#define K2D  (Dm/2)      // 384 k-pairs
#define K2M  (Mm/2)      // 1536 k-pairs

// ---------------- scratch ----------------
__device__ float g_x [(size_t)NTOK*Dm];
__device__ float g_h [(size_t)NTOK*Dm];
__device__ float g_q [(size_t)NTOK*Dm];
__device__ float g_k [(size_t)NTOK*Dm];
__device__ float g_v [(size_t)NTOK*Dm];
__device__ float g_y [(size_t)TROWS*Dm];
// bf16-split planes (packed k-pairs: lo16 = even k, hi16 = odd k)
__device__ uint32_t g_h_hi [(size_t)NTOK*K2D],  g_h_lo [(size_t)NTOK*K2D];
__device__ uint32_t g_ao_hi[(size_t)NTOK*K2D],  g_ao_lo[(size_t)NTOK*K2D];
__device__ uint32_t g_ml_hi[(size_t)NTOK*K2M],  g_ml_lo[(size_t)NTOK*K2M];
__device__ uint32_t g_bf_hi[(size_t)(TROWS+128)*K2D], g_bf_lo[(size_t)(TROWS+128)*K2D];
__device__ uint32_t g_hx_hi[(size_t)(TROWS+128)*K2M], g_hx_lo[(size_t)(TROWS+128)*K2M];
__device__ uint32_t g_whi[(size_t)Em*K2D*Mm], g_wlo[(size_t)Em*K2D*Mm];
__device__ int   g_slot_src[TROWS];
__device__ int   g_comb_idx[NTOK*Km];
__device__ float g_comb_gate[NTOK*Km];

// ---------------- helpers ----------------
__device__ __forceinline__ float gelu_f(float x) {
    const float c = 0.7978845608028654f;
    float t = tanhf(c * (x + 0.044715f * x * x * x));
    return 0.5f * x * (1.0f + t);
}

__device__ __forceinline__ uint32_t smem_u32(const void* p) {
    uint32_t a;
    asm("{ .reg .u64 t; cvta.to.shared.u64 t, %1; cvt.u32.u64 %0, t; }" : "=r"(a) : "l"(p));
    return a;
}

__device__ __forceinline__ void cp16(uint32_t dst, const void* src, uint32_t sz) {
    asm volatile("cp.async.ca.shared.global [%0], [%1], 16, %2;"
                 :: "r"(dst), "l"(src), "r"(sz));
}
#define CP_COMMIT() asm volatile("cp.async.commit_group;" ::: "memory")
#define CP_WAIT(n)  asm volatile("cp.async.wait_group %0;" :: "n"(n) : "memory")

__device__ __forceinline__ void mma16(float* c, const uint32_t* a, const uint32_t* b) {
    asm volatile(
        "mma.sync.aligned.m16n8k16.row.col.f32.bf16.bf16.f32 "
        "{%0,%1,%2,%3},{%4,%5,%6,%7},{%8,%9},{%0,%1,%2,%3};"
        : "+f"(c[0]), "+f"(c[1]), "+f"(c[2]), "+f"(c[3])
        : "r"(a[0]), "r"(a[1]), "r"(a[2]), "r"(a[3]), "r"(b[0]), "r"(b[1]));
}

// pack two floats (x0=even k -> lo16, x1=odd k -> hi16)
__device__ __forceinline__ uint32_t packbf(float x1, float x0) {
    uint32_t d;
    asm("cvt.rn.bf16x2.f32 %0, %1, %2;" : "=r"(d) : "f"(x1), "f"(x0));
    return d;
}
// bf16 split: (x0,x1) -> hi pair + lo pair (exact residual split)
__device__ __forceinline__ void split_bf(float x0, float x1, uint32_t& hi, uint32_t& lo) {
    hi = packbf(x1, x0);
    float h0 = __uint_as_float(hi << 16);
    float h1 = __uint_as_float(hi & 0xFFFF0000u);
    lo = packbf(x1 - h1, x0 - h0);
}

// ---------------- weight split prepass: W[K][P] -> planes [K/2][P] ----------
__global__ void wsplit_kernel(const float* __restrict__ w, uint32_t* __restrict__ whi,
                              uint32_t* __restrict__ wlo, int P, long np) {
    long j = ((long)blockIdx.x * blockDim.x + threadIdx.x) * 4;
    if (j >= np) return;
    long k2 = j / P;
    int n = (int)(j - k2 * P);
    const float* r0 = w + (2 * k2) * (long)P + n;
    float4 a = *reinterpret_cast<const float4*>(r0);
    float4 b = *reinterpret_cast<const float4*>(r0 + P);
    uint32_t h0,l0,h1,l1,h2,l2,h3,l3;
    split_bf(a.x, b.x, h0, l0);
    split_bf(a.y, b.y, h1, l1);
    split_bf(a.z, b.z, h2, l2);
    split_bf(a.w, b.w, h3, l3);
    *reinterpret_cast<uint4*>(whi + j) = make_uint4(h0, h1, h2, h3);
    *reinterpret_cast<uint4*>(wlo + j) = make_uint4(l0, l1, l2, l3);
}

// ---------------- 3xBF16 GEMM (separate hi/lo planes, K=32 chunks) ---------
// A smem: [2 buf][128 rows][20] per plane;  B smem: [2 buf][16 rows][136] per plane
#define KCH 16
#define AST 20
#define BST 136
#define A_PLANE (128*AST)   // 2560 u32
#define B_PLANE (KCH*BST)   // 2176 u32
#define GEMM_SMEM ((4*A_PLANE + 4*B_PLANE)*4)   // 75776 bytes

__global__ void __launch_bounds__(256, 2)
mma_gemm(const uint32_t* __restrict__ Ahi, const uint32_t* __restrict__ Alo,
         const uint32_t* __restrict__ Whi, const uint32_t* __restrict__ Wlo,
         const float* __restrict__ bias,
         float* __restrict__ Cf, uint32_t* __restrict__ Chi, uint32_t* __restrict__ Clo,
         int Nrows, int K2, int Pc,
         long strA, long strW, long strBias, long strC,
         float alpha, int act, int accum) {
    int z = blockIdx.z;
    Ahi += (long)z * strA; Alo += (long)z * strA;
    Whi += (long)z * strW; Wlo += (long)z * strW;
    const float* Bp = bias + (long)z * strBias;

    extern __shared__ uint32_t smw[];
    uint32_t* sAhi = smw;
    uint32_t* sAlo = smw + 2 * A_PLANE;
    uint32_t* sBhi = smw + 4 * A_PLANE;
    uint32_t* sBlo = smw + 4 * A_PLANE + 2 * B_PLANE;

    int tid = threadIdx.x;
    int row0 = blockIdx.y * 128, col0 = blockIdx.x * 128;

    // staging: A 2 threads/row, 8 u32 each (2 cp16/plane); B 16 threads/row, 8 u32 each
    int ar = tid >> 1, ao_ = (tid & 1) * 8;
    int bkr = tid >> 4, bseg = (tid & 15) * 8;
    const uint32_t* gAhi = Ahi + (long)(row0 + ar) * K2 + ao_;
    const uint32_t* gAlo = Alo + (long)(row0 + ar) * K2 + ao_;
    const uint32_t* gBhi = Whi + (long)bkr * Pc + col0 + bseg;
    const uint32_t* gBlo = Wlo + (long)bkr * Pc + col0 + bseg;
    uint32_t asz = ((row0 + ar) < Nrows) ? 16u : 0u;
    uint32_t dAhi = smem_u32(sAhi) + (uint32_t)(ar * AST + ao_) * 4u;
    uint32_t dAlo = smem_u32(sAlo) + (uint32_t)(ar * AST + ao_) * 4u;
    uint32_t dBhi = smem_u32(sBhi) + (uint32_t)(bkr * BST + bseg) * 4u;
    uint32_t dBlo = smem_u32(sBlo) + (uint32_t)(bkr * BST + bseg) * 4u;
    long bstep = (long)KCH * Pc;

    int nk = K2 / KCH;

    cp16(dAhi, gAhi, asz); cp16(dAhi + 16, gAhi + 4, asz);
    cp16(dAlo, gAlo, asz); cp16(dAlo + 16, gAlo + 4, asz);
    cp16(dBhi, gBhi, 16);  cp16(dBhi + 16, gBhi + 4, 16);
    cp16(dBlo, gBlo, 16);  cp16(dBlo + 16, gBlo + 4, 16);
    CP_COMMIT();

    int warp = tid >> 5, lane = tid & 31;
    int wm = (warp & 3) * 32, wn = (warp >> 2) * 64;
    int gid = lane >> 2, tig = lane & 3;

    float acc[2][8][4];
    #pragma unroll
    for (int mt = 0; mt < 2; mt++)
        #pragma unroll
        for (int nt = 0; nt < 8; nt++)
            #pragma unroll
            for (int r = 0; r < 4; r++) acc[mt][nt][r] = 0.0f;

    for (int i = 0; i < nk; i++) {
        int b = i & 1;
        if (i + 1 < nk) {
            int nb = b ^ 1;
            const uint32_t* pah = gAhi + (i + 1) * KCH;
            const uint32_t* pal = gAlo + (i + 1) * KCH;
            const uint32_t* pbh = gBhi + (long)(i + 1) * bstep;
            const uint32_t* pbl = gBlo + (long)(i + 1) * bstep;
            uint32_t oA = (uint32_t)(nb * A_PLANE) * 4u;
            uint32_t oB = (uint32_t)(nb * B_PLANE) * 4u;
            cp16(dAhi + oA, pah, asz); cp16(dAhi + oA + 16, pah + 4, asz);
            cp16(dAlo + oA, pal, asz); cp16(dAlo + oA + 16, pal + 4, asz);
            cp16(dBhi + oB, pbh, 16);  cp16(dBhi + oB + 16, pbh + 4, 16);
            cp16(dBlo + oB, pbl, 16);  cp16(dBlo + oB + 16, pbl + 4, 16);
            CP_COMMIT();
            CP_WAIT(1);
        } else {
            CP_WAIT(0);
        }
        __syncthreads();

        const uint32_t* Ah = sAhi + b * A_PLANE;
        const uint32_t* Al = sAlo + b * A_PLANE;
        const uint32_t* Bh = sBhi + b * B_PLANE;
        const uint32_t* Bl = sBlo + b * B_PLANE;

        #pragma unroll
        for (int ks = 0; ks < 2; ks++) {
            int kq = ks * 8;
            uint32_t afh[2][4], afl[2][4];
            #pragma unroll
            for (int mt = 0; mt < 2; mt++) {
                int base = (wm + mt * 16 + gid) * AST + kq + tig;
                afh[mt][0] = Ah[base];           afh[mt][1] = Ah[base + 8 * AST];
                afh[mt][2] = Ah[base + 4];       afh[mt][3] = Ah[base + 8 * AST + 4];
                afl[mt][0] = Al[base];           afl[mt][1] = Al[base + 8 * AST];
                afl[mt][2] = Al[base + 4];       afl[mt][3] = Al[base + 8 * AST + 4];
            }
            #pragma unroll
            for (int nt = 0; nt < 8; nt++) {
                int bb = (kq + tig) * BST + wn + nt * 8 + gid;
                uint32_t bh[2] = { Bh[bb], Bh[bb + 4 * BST] };
                uint32_t bl[2] = { Bl[bb], Bl[bb + 4 * BST] };
                #pragma unroll
                for (int mt = 0; mt < 2; mt++) {
                    mma16(acc[mt][nt], afh[mt], bl);
                    mma16(acc[mt][nt], afl[mt], bh);
                    mma16(acc[mt][nt], afh[mt], bh);
                }
            }
        }
        __syncthreads();
    }

    // epilogue
    int P2 = Pc >> 1;
    #pragma unroll
    for (int mt = 0; mt < 2; mt++) {
        int r0 = row0 + wm + mt * 16 + gid;
        #pragma unroll
        for (int half = 0; half < 2; half++) {
            int gr = r0 + half * 8;
            if (gr >= Nrows) continue;
            #pragma unroll
            for (int nt = 0; nt < 8; nt++) {
                int gc = col0 + wn + nt * 8 + 2 * tig;
                float2 bv = *reinterpret_cast<const float2*>(Bp + gc);
                float v0 = (acc[mt][nt][half * 2 + 0] + bv.x) * alpha;
                float v1 = (acc[mt][nt][half * 2 + 1] + bv.y) * alpha;
                if (act) { v0 = gelu_f(v0); v1 = gelu_f(v1); }
                if (Chi) {
                    long o = (long)z * strC + (long)gr * P2 + (gc >> 1);
                    uint32_t hi, lo;
                    split_bf(v0, v1, hi, lo);
                    Chi[o] = hi; Clo[o] = lo;
                } else {
                    float* Cp = Cf + (long)z * strC + (long)gr * Pc + gc;
                    if (accum) {
                        float2 o = *reinterpret_cast<float2*>(Cp);
                        v0 += o.x; v1 += o.y;
                    }
                    *reinterpret_cast<float2*>(Cp) = make_float2(v0, v1);
                }
            }
        }
    }
}

// ---------------- elementwise ----------------
__global__ void addpos_kernel(const float* __restrict__ x, const float* __restrict__ pe,
                              float* __restrict__ out) {
    int i = blockIdx.x * blockDim.x + threadIdx.x;
    if (i < NTOK * Dm) out[i] = x[i] + pe[i % (Sm * Dm)];
}

__device__ __forceinline__ float block_reduce_sum(float v) {
    __shared__ float sh[33];
    int lane = threadIdx.x & 31, w = threadIdx.x >> 5;
    #pragma unroll
    for (int o = 16; o; o >>= 1) v += __shfl_xor_sync(0xffffffffu, v, o);
    if (lane == 0) sh[w] = v;
    __syncthreads();
    int nw = blockDim.x >> 5;
    float r = (threadIdx.x < nw) ? sh[threadIdx.x] : 0.0f;
    if (w == 0) {
        #pragma unroll
        for (int o = 16; o; o >>= 1) r += __shfl_xor_sync(0xffffffffu, r, o);
        if (lane == 0) sh[32] = r;
    }
    __syncthreads();
    float out = sh[32];
    __syncthreads();
    return out;
}

__global__ void ln_kernel(const float* __restrict__ in, float* __restrict__ outf,
                          uint32_t* __restrict__ ohi, uint32_t* __restrict__ olo,
                          const float* __restrict__ s, const float* __restrict__ b) {
    int t = blockIdx.x;
    const float* xr = in + (size_t)t * Dm;
    float sum = 0.0f;
    for (int i = threadIdx.x; i < Dm; i += blockDim.x) sum += xr[i];
    float mu = block_reduce_sum(sum) * (1.0f / Dm);
    float vs = 0.0f;
    for (int i = threadIdx.x; i < Dm; i += blockDim.x) { float d = xr[i] - mu; vs += d * d; }
    float var = block_reduce_sum(vs) * (1.0f / Dm);
    float inv = rsqrtf(var + 1e-6f);
    for (int i = threadIdx.x * 2; i < Dm; i += blockDim.x * 2) {
        float v0 = (xr[i] - mu) * inv * s[i] + b[i];
        float v1 = (xr[i + 1] - mu) * inv * s[i + 1] + b[i + 1];
        if (outf) { outf[(size_t)t * Dm + i] = v0; outf[(size_t)t * Dm + i + 1] = v1; }
        if (ohi) {
            uint32_t hi, lo;
            split_bf(v0, v1, hi, lo);
            ohi[(size_t)t * K2D + (i >> 1)] = hi;
            olo[(size_t)t * K2D + (i >> 1)] = lo;
        }
    }
}

// ---------------- attention (writes bf16-split planes) ----------------
#define KPAD (HDm + 1)
__global__ void attn_kernel(const float* __restrict__ q, const float* __restrict__ k,
                            const float* __restrict__ v,
                            uint32_t* __restrict__ ohi, uint32_t* __restrict__ olo) {
    extern __shared__ float sm[];
    float* Ks = sm;
    float* Vs = sm + Sm * KPAD;
    __shared__ float att[8][Sm];
    __shared__ float qrow[8][HDm];

    int bh = blockIdx.x;
    int b = bh / Hh, h = bh % Hh;
    int tid = threadIdx.x, warp = tid >> 5, lane = tid & 31;
    const long base = (long)(b * Sm) * Dm + h * HDm;
    const long base2 = (long)(b * Sm) * K2D + h * (HDm / 2);

    for (int idx = tid; idx < Sm * HDm; idx += blockDim.x) {
        int j = idx >> 6, c = idx & 63;
        Ks[j * KPAD + c] = k[base + (long)j * Dm + c];
        Vs[j * KPAD + c] = v[base + (long)j * Dm + c];
    }
    __syncthreads();

    for (int i = warp; i < Sm; i += 8) {
        for (int c = lane; c < HDm; c += 32) qrow[warp][c] = q[base + (long)i * Dm + c];
        __syncwarp();
        float lmax = -1e30f;
        for (int j = lane; j < Sm; j += 32) {
            float d = 0.0f;
            #pragma unroll
            for (int c = 0; c < HDm; c++) d += qrow[warp][c] * Ks[j * KPAD + c];
            att[warp][j] = d;
            lmax = fmaxf(lmax, d);
        }
        #pragma unroll
        for (int off = 16; off; off >>= 1)
            lmax = fmaxf(lmax, __shfl_xor_sync(0xffffffffu, lmax, off));
        float lsum = 0.0f;
        for (int j = lane; j < Sm; j += 32) {
            float e = expf(att[warp][j] - lmax);
            att[warp][j] = e;
            lsum += e;
        }
        #pragma unroll
        for (int off = 16; off; off >>= 1)
            lsum += __shfl_xor_sync(0xffffffffu, lsum, off);
        float inv = 1.0f / lsum;
        __syncwarp();
        {
            int c = lane * 2;
            float a0 = 0.0f, a1 = 0.0f;
            for (int j = 0; j < Sm; j++) {
                float w = att[warp][j];
                a0 += w * Vs[j * KPAD + c];
                a1 += w * Vs[j * KPAD + c + 1];
            }
            uint32_t hi, lo;
            split_bf(a0 * inv, a1 * inv, hi, lo);
            ohi[base2 + (long)i * K2D + (c >> 1)] = hi;
            olo[base2 + (long)i * K2D + (c >> 1)] = lo;
        }
        __syncwarp();
    }
}

// ---------------- MoE routing ----------------
__global__ void route_kernel(const float* __restrict__ h, const float* __restrict__ wr) {
    int n = blockIdx.x;
    __shared__ float wrs[Em * Dm];
    __shared__ float tv[GSm][Km];
    __shared__ int   ti[GSm][Km];
    int tid = threadIdx.x, warp = tid >> 5, lane = tid & 31;

    for (int idx = tid; idx < Em * Dm; idx += blockDim.x) {
        int e = idx / Dm, c = idx % Dm;
        wrs[e * Dm + c] = wr[c * Em + e];
    }
    for (int s = tid; s < Em * CAPm; s += blockDim.x) {
        int e = s / CAPm, c = s % CAPm;
        g_slot_src[(e * NGm + n) * CAPm + c] = -1;
    }
    __syncthreads();

    for (int t = warp; t < GSm; t += 8) {
        const float* xr = h + (long)(n * GSm + t) * Dm;
        float a[Em];
        #pragma unroll
        for (int e = 0; e < Em; e++) a[e] = 0.0f;
        for (int c = lane; c < Dm; c += 32) {
            float xv = xr[c];
            #pragma unroll
            for (int e = 0; e < Em; e++) a[e] += xv * wrs[e * Dm + c];
        }
        #pragma unroll
        for (int e = 0; e < Em; e++)
            #pragma unroll
            for (int o = 16; o; o >>= 1) a[e] += __shfl_xor_sync(0xffffffffu, a[e], o);
        if (lane == 0) {
            float mx = a[0];
            #pragma unroll
            for (int e = 1; e < Em; e++) mx = fmaxf(mx, a[e]);
            float p[Em], sum = 0.0f;
            #pragma unroll
            for (int e = 0; e < Em; e++) { p[e] = expf(a[e] - mx); sum += p[e]; }
            float inv = 1.0f / sum;
            #pragma unroll
            for (int e = 0; e < Em; e++) p[e] *= inv;
            int i0 = 0;
            #pragma unroll
            for (int e = 1; e < Em; e++) if (p[e] > p[i0]) i0 = e;
            int i1 = (i0 == 0) ? 1 : 0;
            #pragma unroll
            for (int e = 0; e < Em; e++) if (e != i0 && p[e] > p[i1]) i1 = e;
            ti[t][0] = i0; tv[t][0] = p[i0];
            ti[t][1] = i1; tv[t][1] = p[i1];
        }
    }
    __syncthreads();

    if (tid == 0) {
        int cnt[Em];
        #pragma unroll
        for (int e = 0; e < Em; e++) cnt[e] = 0;
        for (int kk = 0; kk < Km; kk++) {
            for (int t = 0; t < GSm; t++) {
                int e = ti[t][kk];
                int pos = cnt[e]++;
                int gt = n * GSm + t;
                if (pos < CAPm) {
                    int row = (e * NGm + n) * CAPm + pos;
                    g_slot_src[row] = gt;
                    g_comb_idx[gt * Km + kk] = row;
                    g_comb_gate[gt * Km + kk] = tv[t][kk];
                } else {
                    g_comb_idx[gt * Km + kk] = -1;
                    g_comb_gate[gt * Km + kk] = 0.0f;
                }
            }
        }
    }
}

__global__ void gather_kernel(const float* __restrict__ h) {
    int i = blockIdx.x * blockDim.x + threadIdx.x;
    if (i >= TROWS * K2D) return;
    int row = i / K2D, kp = i - row * K2D;
    int src = g_slot_src[row];
    float v0 = 0.0f, v1 = 0.0f;
    if (src >= 0) {
        float2 p = *reinterpret_cast<const float2*>(h + (long)src * Dm + 2 * kp);
        v0 = p.x; v1 = p.y;
    }
    uint32_t hi, lo;
    split_bf(v0, v1, hi, lo);
    g_bf_hi[i] = hi; g_bf_lo[i] = lo;
}

__global__ void combine_kernel(float* __restrict__ x) {
    int i = blockIdx.x * blockDim.x + threadIdx.x;
    if (i >= NTOK * Dm) return;
    int t = i / Dm, c = i - t * Dm;
    float acc = 0.0f;
    #pragma unroll
    for (int kk = 0; kk < Km; kk++) {
        int r = g_comb_idx[t * Km + kk];
        if (r >= 0) acc += g_comb_gate[t * Km + kk] * g_y[(long)r * Dm + c];
    }
    x[i] += acc;
}

// ---------------- host ----------------
static inline void wsplit(const float* w, uint32_t* whi, uint32_t* wlo, int P, long np) {
    wsplit_kernel<<<(unsigned)((np / 4 + 255) / 256), 256>>>(w, whi, wlo, P, np);
}

extern "C" void kernel_launch(void* const* d_in, const int* in_sizes, int n_in,
                              void* d_out, int out_size) {
    (void)in_sizes; (void)n_in; (void)out_size;
    const float* in_x     = (const float*)d_in[0];
    const float* posemb   = (const float*)d_in[1];
    const float* ln1_s    = (const float*)d_in[2];
    const float* ln1_b    = (const float*)d_in[3];
    const float* wq       = (const float*)d_in[4];
    const float* bq       = (const float*)d_in[5];
    const float* wk       = (const float*)d_in[6];
    const float* bk       = (const float*)d_in[7];
    const float* wv       = (const float*)d_in[8];
    const float* bv       = (const float*)d_in[9];
    const float* wo       = (const float*)d_in[10];
    const float* bo       = (const float*)d_in[11];
    const float* ln2_s    = (const float*)d_in[12];
    const float* ln2_b    = (const float*)d_in[13];
    const float* dw1      = (const float*)d_in[14];
    const float* db1      = (const float*)d_in[15];
    const float* dw2      = (const float*)d_in[16];
    const float* db2      = (const float*)d_in[17];
    const float* router_w = (const float*)d_in[18];
    const float* mw1      = (const float*)d_in[19];
    const float* mb1      = (const float*)d_in[20];
    const float* mw2      = (const float*)d_in[21];
    const float* mb2      = (const float*)d_in[22];
    const float* out_s    = (const float*)d_in[23];
    const float* out_b    = (const float*)d_in[24];
    float* out = (float*)d_out;

    float *x, *h, *q, *k, *v, *y;
    uint32_t *h_hi, *h_lo, *ao_hi, *ao_lo, *ml_hi, *ml_lo, *bf_hi, *bf_lo, *hx_hi, *hx_lo, *whi, *wlo;
    cudaGetSymbolAddress((void**)&x,     g_x);
    cudaGetSymbolAddress((void**)&h,     g_h);
    cudaGetSymbolAddress((void**)&q,     g_q);
    cudaGetSymbolAddress((void**)&k,     g_k);
    cudaGetSymbolAddress((void**)&v,     g_v);
    cudaGetSymbolAddress((void**)&y,     g_y);
    cudaGetSymbolAddress((void**)&h_hi,  g_h_hi);
    cudaGetSymbolAddress((void**)&h_lo,  g_h_lo);
    cudaGetSymbolAddress((void**)&ao_hi, g_ao_hi);
    cudaGetSymbolAddress((void**)&ao_lo, g_ao_lo);
    cudaGetSymbolAddress((void**)&ml_hi, g_ml_hi);
    cudaGetSymbolAddress((void**)&ml_lo, g_ml_lo);
    cudaGetSymbolAddress((void**)&bf_hi, g_bf_hi);
    cudaGetSymbolAddress((void**)&bf_lo, g_bf_lo);
    cudaGetSymbolAddress((void**)&hx_hi, g_hx_hi);
    cudaGetSymbolAddress((void**)&hx_lo, g_hx_lo);
    cudaGetSymbolAddress((void**)&whi,   g_whi);
    cudaGetSymbolAddress((void**)&wlo,   g_wlo);

    const int ATTN_SMEM = 2 * Sm * KPAD * (int)sizeof(float);
    cudaFuncSetAttribute(attn_kernel, cudaFuncAttributeMaxDynamicSharedMemorySize, ATTN_SMEM);
    cudaFuncSetAttribute(mma_gemm, cudaFuncAttributeMaxDynamicSharedMemorySize, GEMM_SMEM);

    const float qscale = 0.125f;
    const long WDD = (long)Dm * Dm;
    const long WDM = (long)Dm * Mm;

    addpos_kernel<<<(NTOK * Dm + 255) / 256, 256>>>(in_x, posemb, x);

    int di = 0, mi = 0;
    for (int l = 0; l < Lm; l++) {
        // ---- attention block ----
        ln_kernel<<<NTOK, 256>>>(x, nullptr, h_hi, h_lo,
                                 ln1_s + (size_t)l * Dm, ln1_b + (size_t)l * Dm);
        dim3 gdd(Dm / 128, NTOK / 128, 1);
        wsplit(wq + (size_t)l * WDD, whi, wlo, Dm, WDD / 2);
        mma_gemm<<<gdd, 256, GEMM_SMEM>>>(h_hi, h_lo, whi, wlo, bq + (size_t)l * Dm,
                                          q, nullptr, nullptr,
                                          NTOK, K2D, Dm, 0, 0, 0, 0, qscale, 0, 0);
        wsplit(wk + (size_t)l * WDD, whi, wlo, Dm, WDD / 2);
        mma_gemm<<<gdd, 256, GEMM_SMEM>>>(h_hi, h_lo, whi, wlo, bk + (size_t)l * Dm,
                                          k, nullptr, nullptr,
                                          NTOK, K2D, Dm, 0, 0, 0, 0, 1.0f, 0, 0);
        wsplit(wv + (size_t)l * WDD, whi, wlo, Dm, WDD / 2);
        mma_gemm<<<gdd, 256, GEMM_SMEM>>>(h_hi, h_lo, whi, wlo, bv + (size_t)l * Dm,
                                          v, nullptr, nullptr,
                                          NTOK, K2D, Dm, 0, 0, 0, 0, 1.0f, 0, 0);
        attn_kernel<<<Bm * Hh, 256, ATTN_SMEM>>>(q, k, v, ao_hi, ao_lo);
        wsplit(wo + (size_t)l * WDD, whi, wlo, Dm, WDD / 2);
        mma_gemm<<<gdd, 256, GEMM_SMEM>>>(ao_hi, ao_lo, whi, wlo, bo + (size_t)l * Dm,
                                          x, nullptr, nullptr,
                                          NTOK, K2D, Dm, 0, 0, 0, 0, 1.0f, 0, 1);

        // ---- mlp / moe block ----
        ln_kernel<<<NTOK, 256>>>(x, h, h_hi, h_lo,
                                 ln2_s + (size_t)l * Dm, ln2_b + (size_t)l * Dm);
        if (l & 1) {
            route_kernel<<<NGm, 256>>>(h, router_w + (size_t)mi * Dm * Em);
            gather_kernel<<<(TROWS * K2D + 255) / 256, 256>>>(h);
            wsplit(mw1 + (size_t)mi * Em * WDM, whi, wlo, Mm, (long)Em * WDM / 2);
            dim3 g1(Mm / 128, (EROWS + 127) / 128, Em);
            mma_gemm<<<g1, 256, GEMM_SMEM>>>(bf_hi, bf_lo, whi, wlo, mb1 + (size_t)mi * Em * Mm,
                                             nullptr, hx_hi, hx_lo,
                                             EROWS, K2D, Mm,
                                             (long)EROWS * K2D, (long)K2D * Mm, Mm,
                                             (long)EROWS * K2M, 1.0f, 1, 0);
            wsplit(mw2 + (size_t)mi * Em * WDM, whi, wlo, Dm, (long)Em * WDM / 2);
            dim3 g2(Dm / 128, (EROWS + 127) / 128, Em);
            mma_gemm<<<g2, 256, GEMM_SMEM>>>(hx_hi, hx_lo, whi, wlo, mb2 + (size_t)mi * Em * Dm,
                                             y, nullptr, nullptr,
                                             EROWS, K2M, Dm,
                                             (long)EROWS * K2M, (long)K2M * Dm, Dm,
                                             (long)EROWS * Dm, 1.0f, 0, 0);
            combine_kernel<<<(NTOK * Dm + 255) / 256, 256>>>(x);
            mi++;
        } else {
            wsplit(dw1 + (size_t)di * WDM, whi, wlo, Mm, WDM / 2);
            dim3 g1(Mm / 128, NTOK / 128, 1);
            mma_gemm<<<g1, 256, GEMM_SMEM>>>(h_hi, h_lo, whi, wlo, db1 + (size_t)di * Mm,
                                             nullptr, ml_hi, ml_lo,
                                             NTOK, K2D, Mm, 0, 0, 0, 0, 1.0f, 1, 0);
            wsplit(dw2 + (size_t)di * WDM, whi, wlo, Dm, WDD > 0 ? WDM / 2 : 0);
            dim3 g2(Dm / 128, NTOK / 128, 1);
            mma_gemm<<<g2, 256, GEMM_SMEM>>>(ml_hi, ml_lo, whi, wlo, db2 + (size_t)di * Dm,
                                             x, nullptr, nullptr,
                                             NTOK, K2M, Dm, 0, 0, 0, 0, 1.0f, 0, 1);
            di++;
        }
    }

    ln_kernel<<<NTOK, 256>>>(x, out, nullptr, nullptr, out_s, out_b);
}